// round 8
// baseline (speedup 1.0000x reference)
#include <cuda_runtime.h>
#include <math.h>

// ---------------------------------------------------------------------------
// GaussianRasterizer — deterministic binned tile splatting.
//   gr_clear : zero per-tile candidate bitmasks.
//   gr_bin   : each Gaussian atomicOr's its bit into every tile its bbox
//              overlaps (order-independent => deterministic masks).
//   gr_raster: per 16x8 tile, expand mask -> ascending-index survivor list,
//              gather params to smem, evaluate with 4 pixel-groups.
// All float accumulation orders are fixed => bit-deterministic output.
// ---------------------------------------------------------------------------

#define TILE_W 16
#define TILE_H 8
#define NT 512
#define NG 4
#define GSZ 128
#define CAP 512                 // survivor batch capacity (smem)
#define MAXN 8192
#define MW (MAXN / 32)          // mask words per tile (256)
#define MAXTILES 4096

__device__ unsigned g_mask[MAXTILES * MW];

__device__ __forceinline__ float scalar_as_float(const int* p) {
    int v = *p;
    if (v >= 0 && v <= 1000000) return (float)v;
    return __int_as_float(v);
}

__device__ __forceinline__ float ex2(float q) {
    float r;
    asm("ex2.approx.ftz.f32 %0, %1;" : "=f"(r) : "f"(q));
    return r;
}

__global__ __launch_bounds__(256)
void gr_clear(int nwords_total) {
    int i = blockIdx.x * blockDim.x + threadIdx.x;
    if (i < nwords_total) g_mask[i] = 0u;
}

__global__ __launch_bounds__(256)
void gr_bin(const float* __restrict__ means,
            const float* __restrict__ stds,
            const int*   __restrict__ scale_p,
            const int*   __restrict__ ratio_p,
            int N, int ntx, int nty) {
    int i = blockIdx.x * blockDim.x + threadIdx.x;
    if (i >= N) return;

    const float s  = scalar_as_float(scale_p);
    const float r  = scalar_as_float(ratio_p);
    const float rs = r * s;

    float2 mn = ((const float2*)means)[i];
    float2 st = ((const float2*)stds)[i];

    // Exact bbox: |dx| <= r*sx (min over dy of mahal2 is dx^2/sx^2).
    float xlo = mn.x - rs * st.x, xhi = mn.x + rs * st.x;
    float ylo = mn.y - rs * st.y, yhi = mn.y + rs * st.y;

    // Tile tx covers pixel centers [TW*tx+0.5, TW*tx+TW-0.5].
    // Overlap iff tx >= (xlo-TW+0.5)/TW and tx <= (xhi-0.5)/TW.
    // 1e-3 px margin keeps binning conservative vs float rounding.
    int tx0 = (int)ceilf((xlo - (float)TILE_W + 0.5f - 1e-3f) * (1.0f / TILE_W));
    int tx1 = (int)floorf((xhi - 0.5f + 1e-3f) * (1.0f / TILE_W));
    int ty0 = (int)ceilf((ylo - (float)TILE_H + 0.5f - 1e-3f) * (1.0f / TILE_H));
    int ty1 = (int)floorf((yhi - 0.5f + 1e-3f) * (1.0f / TILE_H));
    tx0 = max(tx0, 0); tx1 = min(tx1, ntx - 1);
    ty0 = max(ty0, 0); ty1 = min(ty1, nty - 1);

    unsigned bit = 1u << (i & 31);
    int word = i >> 5;
    for (int ty = ty0; ty <= ty1; ty++)
        for (int tx = tx0; tx <= tx1; tx++)
            atomicOr(&g_mask[(ty * ntx + tx) * MW + word], bit);
}

__global__ __launch_bounds__(NT, 3)
void gr_raster(const float* __restrict__ opacity,
               const float* __restrict__ means,
               const float* __restrict__ stds,
               const float* __restrict__ rhos,
               const float* __restrict__ colors,
               const int*   __restrict__ scale_p,
               const int*   __restrict__ ratio_p,
               float* __restrict__ out, int N, int W, int H) {
    // Survivor SoA: s0 = {mx, my, qa, qb2}, s1 = {qc, cr, cg, cb};
    // qa/qb2/qc carry (-0.5*log2 e): weight = 2^q.
    __shared__ float4 s0[CAP];
    __shared__ float4 s1[CAP];
    __shared__ int    sidx[CAP];
    __shared__ int    scum[NT];        // inclusive word-count scan
    __shared__ int    swt[NT / 32];
    __shared__ float  sacc[NG - 1][GSZ][3];

    const int tid  = threadIdx.x;
    const int lane = tid & 31;
    const int wid  = tid >> 5;
    const int g    = tid >> 7;           // eval group 0..3
    const int htid = tid & (GSZ - 1);    // pixel within tile
    const int tile = blockIdx.y * gridDim.x + blockIdx.x;

    const int px = blockIdx.x * TILE_W + (htid & (TILE_W - 1));
    const int py = blockIdx.y * TILE_H + (htid / TILE_W);
    const float x = (float)px + 0.5f;
    const float y = (float)py + 0.5f;

    const float s    = scalar_as_float(scale_p);
    const float r    = scalar_as_float(ratio_p);
    const float HL2E = -0.5f * 1.44269504088896340736f;  // -0.5*log2(e)
    const float cth  = HL2E * r * r;     // pass when folded q >= cth

    const float2* __restrict__ mean2 = (const float2*)means;
    const float2* __restrict__ std2  = (const float2*)stds;

    // ---- Load this tile's mask word + popcount, block-wide inclusive scan.
    const int nwords = (N + 31) >> 5;
    unsigned w = 0;
    int c = 0;
    if (tid < nwords) {
        w = g_mask[tile * MW + tid];
        c = __popc(w);
    }
    int incl = c;
    #pragma unroll
    for (int d = 1; d < 32; d <<= 1) {
        int v = __shfl_up_sync(0xffffffffu, incl, d);
        if (lane >= d) incl += v;
    }
    if (lane == 31) swt[wid] = incl;
    __syncthreads();
    int wbase = 0, total = 0;
    #pragma unroll
    for (int q = 0; q < NT / 32; q++) {
        int t = swt[q];
        if (q < wid) wbase += t;
        total += t;
    }
    scum[tid] = wbase + incl;            // inclusive count through word tid
    __syncthreads();

    float ar0 = 0.f, ag0 = 0.f, ab0 = 0.f;
    float ar1 = 0.f, ag1 = 0.f, ab1 = 0.f;

    // ---- Batched survivor processing (single batch in the common case).
    int wbeg = 0, done = 0;
    while (wbeg < nwords) {
        int wend, btot;
        if (total - done <= CAP) {               // common: everything fits
            wend = nwords;
            btot = total - done;
        } else {                                  // rare fallback
            wend = wbeg;
            while (wend < nwords && scum[wend] - done <= CAP) wend++;
            btot = scum[wend - 1] - done;
        }

        // Expand set bits of words [wbeg, wend) in ascending index order.
        if (tid >= wbeg && tid < wend && c > 0) {
            int slot = (scum[tid] - c) - done;
            unsigned ww = w;
            while (ww) {
                int b = __ffs(ww) - 1;
                ww &= ww - 1;
                sidx[slot++] = (tid << 5) + b;
            }
        }
        __syncthreads();

        // Gather parameters for this batch's survivors.
        if (tid < btot) {
            int gi = sidx[tid];
            float2 mn  = mean2[gi];
            float2 st  = std2[gi];
            float rho  = rhos[gi];
            float o    = opacity[gi];
            float c0   = colors[3 * gi + 0];
            float c1   = colors[3 * gi + 1];
            float c2   = colors[3 * gi + 2];
            float sx   = st.x * s;
            float sy   = st.y * s;
            float om   = 1.0f - rho * rho;
            float qa   = __fdividef(HL2E,               sx * sx * om);
            float qc   = __fdividef(HL2E,               sy * sy * om);
            float qb2  = __fdividef(-2.0f * HL2E * rho, sx * sy * om);
            s0[tid] = make_float4(mn.x, mn.y, qa, qb2);
            s1[tid] = make_float4(qc, o * c0, o * c1, o * c2);
        }
        __syncthreads();

        // ---- Eval: group g takes survivors j = g (mod NG); branch-free.
        int j = g;
        for (; j + NG < btot; j += 2 * NG) {
            float4 a0 = s0[j],      b0 = s1[j];
            float4 a1 = s0[j + NG], b1 = s1[j + NG];

            float dx0 = x - a0.x, dy0 = y - a0.y;
            float q0  = a0.z * dx0 * dx0;
            q0 = fmaf(a0.w * dx0, dy0, q0);
            q0 = fmaf(b0.x * dy0, dy0, q0);

            float dx1 = x - a1.x, dy1 = y - a1.y;
            float q1  = a1.z * dx1 * dx1;
            q1 = fmaf(a1.w * dx1, dy1, q1);
            q1 = fmaf(b1.x * dy1, dy1, q1);

            float w0 = ex2(q0);
            float w1 = ex2(q1);
            w0 = (q0 >= cth) ? w0 : 0.0f;
            w1 = (q1 >= cth) ? w1 : 0.0f;

            ar0 = fmaf(w0, b0.y, ar0);
            ag0 = fmaf(w0, b0.z, ag0);
            ab0 = fmaf(w0, b0.w, ab0);
            ar1 = fmaf(w1, b1.y, ar1);
            ag1 = fmaf(w1, b1.z, ag1);
            ab1 = fmaf(w1, b1.w, ab1);
        }
        if (j < btot) {
            float4 a0 = s0[j], b0 = s1[j];
            float dx0 = x - a0.x, dy0 = y - a0.y;
            float q0  = a0.z * dx0 * dx0;
            q0 = fmaf(a0.w * dx0, dy0, q0);
            q0 = fmaf(b0.x * dy0, dy0, q0);
            float w0 = ex2(q0);
            w0 = (q0 >= cth) ? w0 : 0.0f;
            ar0 = fmaf(w0, b0.y, ar0);
            ag0 = fmaf(w0, b0.z, ag0);
            ab0 = fmaf(w0, b0.w, ab0);
        }
        __syncthreads();    // eval done before next batch overwrites smem

        done += btot;
        wbeg = wend;
    }

    // ---- Deterministic combine: groups 1..3 publish, group 0 sums in order.
    const float pr = ar0 + ar1;
    const float pg = ag0 + ag1;
    const float pb = ab0 + ab1;

    if (g) {
        sacc[g - 1][htid][0] = pr;
        sacc[g - 1][htid][1] = pg;
        sacc[g - 1][htid][2] = pb;
    }
    __syncthreads();
    if (g == 0 && px < W && py < H) {
        float sr = pr, sg = pg, sb = pb;
        #pragma unroll
        for (int q = 0; q < NG - 1; q++) {
            sr += sacc[q][htid][0];
            sg += sacc[q][htid][1];
            sb += sacc[q][htid][2];
        }
        int o = (py * W + px) * 3;
        out[o + 0] = sr;
        out[o + 1] = sg;
        out[o + 2] = sb;
    }
}

extern "C" void kernel_launch(void* const* d_in, const int* in_sizes, int n_in,
                              void* d_out, int out_size) {
    const float* opacity = (const float*)d_in[0];
    const float* means   = (const float*)d_in[1];
    const float* stds    = (const float*)d_in[2];
    const float* rhos    = (const float*)d_in[3];
    const float* colors  = (const float*)d_in[4];
    const int*   scale_p = (const int*)d_in[7];
    const int*   ratio_p = (const int*)d_in[8];

    int N = in_sizes[0];
    if (N > MAXN) N = MAXN;

    int hw = out_size / 3;
    int W = (int)lrint(sqrt((double)hw));
    while (W > 1 && (hw % W) != 0) W--;
    int H = hw / W;

    int ntx = (W + TILE_W - 1) / TILE_W;
    int nty = (H + TILE_H - 1) / TILE_H;
    int ntiles = ntx * nty;

    float* out = (float*)d_out;

    int nclr = ntiles * MW;
    gr_clear<<<(nclr + 255) / 256, 256>>>(nclr);
    gr_bin<<<(N + 255) / 256, 256>>>(means, stds, scale_p, ratio_p, N, ntx, nty);

    dim3 grid(ntx, nty);
    gr_raster<<<grid, NT>>>(opacity, means, stds, rhos, colors,
                            scale_p, ratio_p, out, N, W, H);
}